// round 5
// baseline (speedup 1.0000x reference)
#include <cuda_runtime.h>
#include <cuda_fp16.h>
#include <cstdint>
#include <math.h>

#define T_LEN 256
#define B_DIM 512
#define F_DIM 256
#define H_DIM 512
#define P_INT 12
#define KTOT  768
#define NG    2048

// ---------------- GEMM tiling ----------------
#define BM 64
#define BN 128
#define BK 64              // halfs per stage (128 bytes per row)
#define STG 3
#define NCH (KTOT / BK)    // 12 K-chunks
#define NTN (NG / BN)      // 16 n-tiles
#define GRID_G 296         // persistent CTAs (2 per SM on 148 SMs)

#define A_SZ (BM * BK * 2) // 8192 B per stage
#define B_SZ (BN * BK * 2) // 16384 B per stage
#define SMEM_BYTES (STG * (A_SZ + B_SZ))   // 72 KB

// ---------------- static device scratch ----------------
__device__ __half d_Wh[NG * KTOT];                // [2048][768] K-major fp16
__device__ float  d_Bcat[NG];
__device__ __half d_Xh[T_LEN * B_DIM * F_DIM];    // x in fp16
__device__ __half d_Hh[P_INT * B_DIM * H_DIM];    // h ring, fp16 (GEMM operand)
__device__ float  d_Hout[B_DIM * H_DIM];          // fp32 h for ring slot 3 (output)
__device__ __half d_Sbuf[P_INT * B_DIM * NG];     // wave pre-activations, fp16
__device__ float  d_Vbuf[P_INT * H_DIM];
__device__ float  d_Vcarry[H_DIM];
__device__ int    d_flag[P_INT];                  // chain->pointwise step flags

// ---------------- helpers ----------------
__device__ __forceinline__ uint32_t smem_u32(const void* p) {
    uint32_t a;
    asm("{ .reg .u64 t; cvta.to.shared.u64 t, %1; cvt.u32.u64 %0, t; }" : "=r"(a) : "l"(p));
    return a;
}
__device__ __forceinline__ void cpasync16(uint32_t dst, const void* src) {
    asm volatile("cp.async.cg.shared.global [%0], [%1], 16;"
                 :: "r"(dst), "l"(__cvta_generic_to_global(src)) : "memory");
}
__device__ __forceinline__ void ldm4(uint32_t* r, uint32_t addr) {
    asm volatile("ldmatrix.sync.aligned.m8n8.x4.shared.b16 {%0,%1,%2,%3}, [%4];"
                 : "=r"(r[0]), "=r"(r[1]), "=r"(r[2]), "=r"(r[3]) : "r"(addr));
}
// fp16-accumulate MMA: d/c are 2 b32 regs holding {c0,c1},{c2,c3} halves
__device__ __forceinline__ void mma16816h(uint32_t* d, const uint32_t* a, uint32_t b0, uint32_t b1) {
    asm volatile(
        "mma.sync.aligned.m16n8k16.row.col.f16.f16.f16.f16 "
        "{%0,%1}, {%2,%3,%4,%5}, {%6,%7}, {%0,%1};"
        : "+r"(d[0]), "+r"(d[1])
        : "r"(a[0]), "r"(a[1]), "r"(a[2]), "r"(a[3]), "r"(b0), "r"(b1));
}

// ---------------- pack / convert / init ----------------
__global__ void pack_kernel(const float* __restrict__ Wf, const float* __restrict__ bf,
                            const float* __restrict__ Wi, const float* __restrict__ bi,
                            const float* __restrict__ Wo, const float* __restrict__ bo,
                            const float* __restrict__ Wg, const float* __restrict__ bg) {
    int idx = blockIdx.x * blockDim.x + threadIdx.x;
    if (idx < NG * KTOT) {
        int n = idx / KTOT;
        int k = idx % KTOT;
        int g = n >> 9, h = n & 511;
        const float* W = (g == 0) ? Wf : (g == 1) ? Wi : (g == 2) ? Wo : Wg;
        d_Wh[idx] = __float2half(W[k * H_DIM + h]);
    }
    if (idx < NG) {
        int g = idx / H_DIM, h = idx % H_DIM;
        const float* bb = (g == 0) ? bf : (g == 1) ? bi : (g == 2) ? bo : bg;
        d_Bcat[idx] = bb[h];
    }
}

__global__ void convx_kernel(const float* __restrict__ x) {
    int i = blockIdx.x * blockDim.x + threadIdx.x;
    d_Xh[i] = __float2half(x[i]);
}

__global__ void init_kernel() {
    int i = blockIdx.x * blockDim.x + threadIdx.x;
    if (i < P_INT * B_DIM * H_DIM) d_Hh[i] = __float2half(0.0f);
    if (i < H_DIM) d_Vcarry[i] = 0.0f;
    if (i < P_INT) d_flag[i] = 0;
}

// ---------------- stage loader ----------------
__device__ __forceinline__ void load_stage(uint32_t sa, uint32_t sbB, int tid, int ch,
                                           const __half* Xb, const __half* Hb, const __half* Wb) {
    const int k0 = ch * BK;
    const __half* asrc;
    int astride;
    if (k0 < F_DIM) { asrc = Xb + k0;           astride = F_DIM; }
    else            { asrc = Hb + (k0 - F_DIM); astride = H_DIM; }
    #pragma unroll
    for (int i = 0; i < 2; i++) {               // A: 64 rows x 8 chunks of 16B
        int cell = tid + i * 256;
        int r = cell >> 3, c = cell & 7;
        cpasync16(sa + r * 128 + ((c ^ (r & 7)) * 16),
                  asrc + (size_t)r * astride + c * 8);
    }
    #pragma unroll
    for (int i = 0; i < 4; i++) {               // B: 128 n-rows x 8 chunks
        int cell = tid + i * 256;
        int r = cell >> 3, c = cell & 7;
        cpasync16(sbB + r * 128 + ((c ^ (r & 7)) * 16),
                  Wb + (size_t)r * KTOT + k0 + c * 8);
    }
}

// ---------------- HMMA wave GEMM (persistent, fp16-acc): Sbuf = A * W^T + bias ----------------
__global__ void __launch_bounds__(256, 2) gemm_hmma(int t0, int M) {
    extern __shared__ char smem[];
    const uint32_t sb = smem_u32(smem);
    const int tid = threadIdx.x;
    const int wid = tid >> 5;
    const int l   = tid & 31;
    const int wm = (wid >> 2) * 32;   // warp m-offset (0,32)
    const int wn = (wid & 3) * 32;    // warp n-offset (0,32,64,96)
    const int lrow = l & 15;
    const int lk   = l >> 4;

    uint32_t sA[STG], sB[STG];
    #pragma unroll
    for (int s = 0; s < STG; s++) {
        sA[s] = sb + s * (A_SZ + B_SZ);
        sB[s] = sA[s] + A_SZ;
    }

    const int ntiles = (M / BM) * NTN;
    for (int idx = blockIdx.x; idx < ntiles; idx += gridDim.x) {
        const int m0 = (idx / NTN) * BM;
        const int n0 = (idx % NTN) * BN;

        const __half* Xb = d_Xh + ((size_t)t0 * B_DIM + m0) * F_DIM;
        const __half* Hb = d_Hh + (size_t)m0 * H_DIM;
        const __half* Wb = d_Wh + (size_t)n0 * KTOT;

        float acc[2][4][4];
        #pragma unroll
        for (int i = 0; i < 2; i++)
            #pragma unroll
            for (int j = 0; j < 4; j++)
                #pragma unroll
                for (int q = 0; q < 4; q++) acc[i][j][q] = 0.0f;

        __syncthreads();   // all warps done reading smem of previous tile

        #pragma unroll
        for (int c = 0; c < STG - 1; c++) {
            load_stage(sA[c], sB[c], tid, c, Xb, Hb, Wb);
            asm volatile("cp.async.commit_group;" ::: "memory");
        }

        for (int ch = 0; ch < NCH; ch++) {
            asm volatile("cp.async.wait_group 1;" ::: "memory");
            __syncthreads();
            const int cl = ch + STG - 1;
            if (cl < NCH)
                load_stage(sA[cl % STG], sB[cl % STG], tid, cl, Xb, Hb, Wb);
            asm volatile("cp.async.commit_group;" ::: "memory");

            const int s = ch % STG;
            uint32_t hacc[2][4][2];
            #pragma unroll
            for (int mi = 0; mi < 2; mi++)
                #pragma unroll
                for (int nj = 0; nj < 4; nj++) {
                    hacc[mi][nj][0] = 0u;
                    hacc[mi][nj][1] = 0u;
                }

            #pragma unroll
            for (int kk = 0; kk < BK / 16; kk++) {
                uint32_t af[2][4], bfr[2][4];
                #pragma unroll
                for (int mi = 0; mi < 2; mi++) {
                    int r = wm + mi * 16 + lrow;
                    int c = kk * 2 + lk;
                    ldm4(af[mi], sA[s] + r * 128 + ((c ^ (r & 7)) * 16));
                }
                #pragma unroll
                for (int bj = 0; bj < 2; bj++) {
                    int r = wn + bj * 16 + lrow;
                    int c = kk * 2 + lk;
                    ldm4(bfr[bj], sB[s] + r * 128 + ((c ^ (r & 7)) * 16));
                }
                #pragma unroll
                for (int mi = 0; mi < 2; mi++)
                    #pragma unroll
                    for (int nj = 0; nj < 4; nj++)
                        mma16816h(hacc[mi][nj], af[mi],
                                  bfr[nj >> 1][nj & 1], bfr[nj >> 1][(nj & 1) + 2]);
            }

            // promote fp16 chunk-accumulators into fp32 masters
            #pragma unroll
            for (int mi = 0; mi < 2; mi++)
                #pragma unroll
                for (int nj = 0; nj < 4; nj++) {
                    float2 p0 = __half22float2(*reinterpret_cast<__half2*>(&hacc[mi][nj][0]));
                    float2 p1 = __half22float2(*reinterpret_cast<__half2*>(&hacc[mi][nj][1]));
                    acc[mi][nj][0] += p0.x;
                    acc[mi][nj][1] += p0.y;
                    acc[mi][nj][2] += p1.x;
                    acc[mi][nj][3] += p1.y;
                }
        }

        // epilogue: bias + store fp16
        __half2* S2 = (__half2*)d_Sbuf;
        #pragma unroll
        for (int mi = 0; mi < 2; mi++) {
            #pragma unroll
            for (int nj = 0; nj < 4; nj++) {
                int m = m0 + wm + mi * 16 + (l >> 2);
                int n = n0 + wn + nj * 8 + (l & 3) * 2;
                float b0 = d_Bcat[n], b1 = d_Bcat[n + 1];
                S2[((size_t)m * NG + n) >> 1] =
                    __floats2half2_rn(acc[mi][nj][0] + b0, acc[mi][nj][1] + b1);
                S2[((size_t)(m + 8) * NG + n) >> 1] =
                    __floats2half2_rn(acc[mi][nj][2] + b0, acc[mi][nj][3] + b1);
            }
        }
    }
}

// ---------------- warp softmax over 512 values (16 per lane) ----------------
__device__ __forceinline__ void softmax16(float* s) {
    float mx = -1e30f;
    #pragma unroll
    for (int q = 0; q < 16; q++) mx = fmaxf(mx, s[q]);
    #pragma unroll
    for (int o = 16; o > 0; o >>= 1) mx = fmaxf(mx, __shfl_xor_sync(0xffffffffu, mx, o));
    float sum = 0.0f;
    #pragma unroll
    for (int q = 0; q < 16; q++) { s[q] = __expf(s[q] - mx); sum += s[q]; }
    #pragma unroll
    for (int o = 16; o > 0; o >>= 1) sum += __shfl_xor_sync(0xffffffffu, sum, o);
    const float inv = 1.0f / sum;
    #pragma unroll
    for (int q = 0; q < 16; q++) s[q] *= inv;
}

// lane-value layout: element q (0..15) of lane l maps to index (q>>1)*64 + l*2 + (q&1)
__device__ __forceinline__ void load_gate16(const __half2* base, int l, float* s) {
    #pragma unroll
    for (int q2 = 0; q2 < 8; q2++) {
        float2 v = __half22float2(base[q2 * 32 + l]);
        s[2 * q2] = v.x;
        s[2 * q2 + 1] = v.y;
    }
}

// ---------------- fused chain + pointwise (one launch per wave) ----------------
// block 0: sequential v-row chain, publishing d_flag[j] = wv+1 after Vbuf[j] is ready
// blocks 1..: pointwise rows, spin on d_flag[j]
__global__ void __launch_bounds__(256) fused_cp(int t0, int ns, int wv) {
    if (blockIdx.x == 0) {
        if (threadIdx.x >= 32) return;
        const int l = threadIdx.x;
        float v[16];
        #pragma unroll
        for (int q2 = 0; q2 < 8; q2++) {
            float2 vc = *(const float2*)(d_Vcarry + q2 * 64 + l * 2);
            v[2 * q2] = vc.x;
            v[2 * q2 + 1] = vc.y;
        }
        for (int j = 0; j < ns; j++) {
            #pragma unroll
            for (int q2 = 0; q2 < 8; q2++)
                *(float2*)(d_Vbuf + j * H_DIM + q2 * 64 + l * 2) =
                    make_float2(v[2 * q2], v[2 * q2 + 1]);
            __threadfence();
            __syncwarp();
            if (l == 0)
                asm volatile("st.release.gpu.s32 [%0], %1;"
                             :: "l"(d_flag + j), "r"(wv + 1) : "memory");
            const int r = (t0 + j + 1) % P_INT;
            const __half2* S = (const __half2*)d_Sbuf + (((size_t)(j * B_DIM + r) * NG) >> 1);
            float sf[16], si[16], sg[16];
            load_gate16(S, l, sf);
            load_gate16(S + (H_DIM >> 1), l, si);
            load_gate16(S + ((3 * H_DIM) >> 1), l, sg);
            softmax16(sf);
            softmax16(si);
            #pragma unroll
            for (int q = 0; q < 16; q++)
                v[q] = tanhf(sf[q] * v[q] + si[q] * tanhf(sg[q]));
        }
        #pragma unroll
        for (int q2 = 0; q2 < 8; q2++)
            *(float2*)(d_Vcarry + q2 * 64 + l * 2) = make_float2(v[2 * q2], v[2 * q2 + 1]);
        return;
    }

    const int bid = blockIdx.x - 1;
    const int l = threadIdx.x & 31;
    const int m = (bid * 256 + threadIdx.x) >> 5;   // 8 rows per block, same j per block
    const int j = m >> 9;

    // gates don't depend on the chain — load & softmax first, then wait for Vbuf[j]
    const __half2* S = (const __half2*)d_Sbuf + (((size_t)m * NG) >> 1);
    float sf[16], si[16], so[16], sg[16];
    load_gate16(S, l, sf);
    load_gate16(S + (H_DIM >> 1), l, si);
    load_gate16(S + ((2 * H_DIM) >> 1), l, so);
    load_gate16(S + ((3 * H_DIM) >> 1), l, sg);
    softmax16(sf);
    softmax16(si);
    softmax16(so);

    if (threadIdx.x == 0) {
        int fl;
        do {
            asm volatile("ld.acquire.gpu.s32 %0, [%1];" : "=r"(fl) : "l"(d_flag + j) : "memory");
        } while (fl < wv + 1);
    }
    __syncthreads();

    __half2* Hh2 = (__half2*)d_Hh;
    const bool wout = (j == 3);   // ring slot 3 feeds the output
    #pragma unroll
    for (int q2 = 0; q2 < 8; q2++) {
        float2 vv = *(const float2*)(d_Vbuf + j * H_DIM + q2 * 64 + l * 2);
        float c0 = tanhf(sf[2 * q2] * vv.x + si[2 * q2] * tanhf(sg[2 * q2]));
        float c1 = tanhf(sf[2 * q2 + 1] * vv.y + si[2 * q2 + 1] * tanhf(sg[2 * q2 + 1]));
        float h0 = so[2 * q2] * c0;
        float h1 = so[2 * q2 + 1] * c1;
        Hh2[((size_t)m * H_DIM + q2 * 64 + l * 2) >> 1] = __floats2half2_rn(h0, h1);
        if (wout)
            *(float2*)(d_Hout + (size_t)(m & 511) * H_DIM + q2 * 64 + l * 2) =
                make_float2(h0, h1);
    }
}

__global__ void copy_out_kernel(float* __restrict__ out) {
    int i = blockIdx.x * blockDim.x + threadIdx.x;
    out[i] = d_Hout[i];
}

// ---------------- launch ----------------
extern "C" void kernel_launch(void* const* d_in, const int* in_sizes, int n_in,
                              void* d_out, int out_size) {
    const float* x  = (const float*)d_in[0];
    const float* Wf = (const float*)d_in[1];
    const float* bf = (const float*)d_in[2];
    const float* Wi = (const float*)d_in[3];
    const float* bi = (const float*)d_in[4];
    const float* Wo = (const float*)d_in[5];
    const float* bo = (const float*)d_in[6];
    const float* Wg = (const float*)d_in[7];
    const float* bg = (const float*)d_in[8];
    float* out = (float*)d_out;

    cudaFuncSetAttribute(gemm_hmma, cudaFuncAttributeMaxDynamicSharedMemorySize, SMEM_BYTES);

    {
        int n = NG * KTOT;
        pack_kernel<<<(n + 255) / 256, 256>>>(Wf, bf, Wi, bi, Wo, bo, Wg, bg);
    }
    {
        int n = T_LEN * B_DIM * F_DIM;
        convx_kernel<<<n / 256, 256>>>(x);
    }
    {
        int n = P_INT * B_DIM * H_DIM;
        init_kernel<<<(n + 255) / 256, 256>>>();
    }

    int t0 = 0;
    int wv = 0;
    while (t0 < T_LEN) {
        const int ns = (T_LEN - t0 < P_INT) ? (T_LEN - t0) : P_INT;
        const int M = ns * B_DIM;
        gemm_hmma<<<GRID_G, 256, SMEM_BYTES>>>(t0, M);
        fused_cp<<<M / 8 + 1, 256>>>(t0, ns, wv);
        t0 += ns;
        wv++;
    }

    copy_out_kernel<<<(B_DIM * H_DIM) / 256, 256>>>(out);
}

// round 6
// speedup vs baseline: 1.1545x; 1.1545x over previous
#include <cuda_runtime.h>
#include <cuda_fp16.h>
#include <cstdint>
#include <math.h>

#define T_LEN 256
#define B_DIM 512
#define F_DIM 256
#define H_DIM 512
#define P_INT 12
#define KTOT  768
#define NG    2048
#define NW    22            // ceil(256/12)

// ---------------- GEMM tiling (R4 config: f32-acc, at mma.sync roofline) ----------------
#define BM 128
#define BN 128
#define BK 64
#define STG 3
#define NCH (KTOT / BK)     // 12

#define A_SZ (BM * BK * 2)  // 16384
#define B_SZ (BN * BK * 2)  // 16384
#define SMEM_BYTES (STG * (A_SZ + B_SZ))  // 96 KB

#define WAVE_ROWS (P_INT * B_DIM)          // 6144
#define WAVE_S ((size_t)WAVE_ROWS * NG)    // elements per Sbuf bank
#define NMT_MAX 48                          // mtiles per full wave

// ---------------- static device scratch ----------------
__device__ __half d_Wh[NG * KTOT];
__device__ float  d_Bcat[NG];
__device__ __half d_Xh[T_LEN * B_DIM * F_DIM];
__device__ __half d_Hh[P_INT * B_DIM * H_DIM];
__device__ __half d_Sbuf[2 * WAVE_S];          // double-buffered by wave parity
__device__ float  d_Vbuf[2 * P_INT * H_DIM];   // double-buffered by wave parity
__device__ int    d_gemmdone[NMT_MAX];         // n-tiles done per mtile (monotonic)
__device__ int    d_pwdone[NMT_MAX];           // pointwise blocks done per mtile (monotonic)
__device__ int    d_vflag[P_INT];              // chain step generation

// ---------------- helpers ----------------
__device__ __forceinline__ uint32_t smem_u32(const void* p) {
    uint32_t a;
    asm("{ .reg .u64 t; cvta.to.shared.u64 t, %1; cvt.u32.u64 %0, t; }" : "=r"(a) : "l"(p));
    return a;
}
__device__ __forceinline__ void cpasync16(uint32_t dst, const void* src) {
    asm volatile("cp.async.cg.shared.global [%0], [%1], 16;"
                 :: "r"(dst), "l"(__cvta_generic_to_global(src)) : "memory");
}
__device__ __forceinline__ void ldm4(uint32_t* r, uint32_t addr) {
    asm volatile("ldmatrix.sync.aligned.m8n8.x4.shared.b16 {%0,%1,%2,%3}, [%4];"
                 : "=r"(r[0]), "=r"(r[1]), "=r"(r[2]), "=r"(r[3]) : "r"(addr));
}
__device__ __forceinline__ void mma16816(float* d, const uint32_t* a, uint32_t b0, uint32_t b1) {
    asm volatile(
        "mma.sync.aligned.m16n8k16.row.col.f32.f16.f16.f32 "
        "{%0,%1,%2,%3}, {%4,%5,%6,%7}, {%8,%9}, {%0,%1,%2,%3};"
        : "+f"(d[0]), "+f"(d[1]), "+f"(d[2]), "+f"(d[3])
        : "r"(a[0]), "r"(a[1]), "r"(a[2]), "r"(a[3]), "r"(b0), "r"(b1));
}
__device__ __forceinline__ int ld_acq(const int* p) {
    int v;
    asm volatile("ld.acquire.gpu.s32 %0, [%1];" : "=r"(v) : "l"(p) : "memory");
    return v;
}
__device__ __forceinline__ void spin_ge(const int* p, int tgt) {
    if (ld_acq(p) >= tgt) return;
    while (ld_acq(p) < tgt) __nanosleep(128);
}

// ---------------- pack / convert / init ----------------
__global__ void pack_kernel(const float* __restrict__ Wf, const float* __restrict__ bf,
                            const float* __restrict__ Wi, const float* __restrict__ bi,
                            const float* __restrict__ Wo, const float* __restrict__ bo,
                            const float* __restrict__ Wg, const float* __restrict__ bg) {
    int idx = blockIdx.x * blockDim.x + threadIdx.x;
    if (idx < NG * KTOT) {
        int n = idx / KTOT;
        int k = idx % KTOT;
        int g = n >> 9, h = n & 511;
        const float* W = (g == 0) ? Wf : (g == 1) ? Wi : (g == 2) ? Wo : Wg;
        d_Wh[idx] = __float2half(W[k * H_DIM + h]);
    }
    if (idx < NG) {
        int g = idx / H_DIM, h = idx % H_DIM;
        const float* bb = (g == 0) ? bf : (g == 1) ? bi : (g == 2) ? bo : bg;
        d_Bcat[idx] = bb[h];
    }
}

__global__ void convx_kernel(const float* __restrict__ x) {
    int i = blockIdx.x * blockDim.x + threadIdx.x;
    d_Xh[i] = __float2half(x[i]);
}

__global__ void init_kernel() {
    int i = blockIdx.x * blockDim.x + threadIdx.x;
    if (i < P_INT * B_DIM * H_DIM) d_Hh[i] = __float2half(0.0f);
    if (i < NMT_MAX) { d_gemmdone[i] = 0; d_pwdone[i] = 0; }
    if (i < P_INT) d_vflag[i] = 0;
}

// ---------------- stage loader ----------------
__device__ __forceinline__ void load_stage(uint32_t sa, uint32_t sbB, int tid, int ch,
                                           const __half* Xb, const __half* Hb, const __half* Wb) {
    const int k0 = ch * BK;
    const __half* asrc;
    int astride;
    if (k0 < F_DIM) { asrc = Xb + k0;           astride = F_DIM; }
    else            { asrc = Hb + (k0 - F_DIM); astride = H_DIM; }
    #pragma unroll
    for (int i = 0; i < 4; i++) {
        int cell = tid + i * 256;
        int r = cell >> 3, c = cell & 7;
        cpasync16(sa + r * 128 + ((c ^ (r & 7)) * 16),
                  asrc + (size_t)r * astride + c * 8);
    }
    #pragma unroll
    for (int i = 0; i < 4; i++) {
        int cell = tid + i * 256;
        int r = cell >> 3, c = cell & 7;
        cpasync16(sbB + r * 128 + ((c ^ (r & 7)) * 16),
                  Wb + (size_t)r * KTOT + k0 + c * 8);
    }
}

// ---------------- warp softmax over 512 values (16 per lane) ----------------
__device__ __forceinline__ void softmax16(float* s) {
    float mx = -1e30f;
    #pragma unroll
    for (int q = 0; q < 16; q++) mx = fmaxf(mx, s[q]);
    #pragma unroll
    for (int o = 16; o > 0; o >>= 1) mx = fmaxf(mx, __shfl_xor_sync(0xffffffffu, mx, o));
    float sum = 0.0f;
    #pragma unroll
    for (int q = 0; q < 16; q++) { s[q] = __expf(s[q] - mx); sum += s[q]; }
    #pragma unroll
    for (int o = 16; o > 0; o >>= 1) sum += __shfl_xor_sync(0xffffffffu, sum, o);
    const float inv = 1.0f / sum;
    #pragma unroll
    for (int q = 0; q < 16; q++) s[q] *= inv;
}
// element q of lane l <-> column (q>>1)*64 + l*2 + (q&1)
__device__ __forceinline__ void load_gate16(const __half2* base, int l, float* s) {
    #pragma unroll
    for (int q2 = 0; q2 < 8; q2++) {
        float2 v = __half22float2(base[q2 * 32 + l]);
        s[2 * q2] = v.x;
        s[2 * q2 + 1] = v.y;
    }
}

// ---------------- persistent fused kernel ----------------
__global__ void __launch_bounds__(256, 2) persist(float* __restrict__ out) {
    extern __shared__ char smem[];
    const int G = gridDim.x;
    const int W = G - 1;                 // worker CTAs; last CTA runs the chain
    const int tid = threadIdx.x;

    if ((int)blockIdx.x == W) {
        // ===== chain CTA: one warp, register-resident v across ALL waves =====
        if (tid >= 32) return;
        const int l = tid;
        float v[16];
        #pragma unroll
        for (int q = 0; q < 16; q++) v[q] = 0.0f;

        for (int w = 0; w < NW; w++) {
            const int t0 = w * P_INT;
            const int ns = (T_LEN - t0 < P_INT) ? (T_LEN - t0) : P_INT;
            const __half2* Sb2 = (const __half2*)(d_Sbuf + (size_t)(w & 1) * WAVE_S);
            float* Vb = d_Vbuf + (w & 1) * P_INT * H_DIM;
            for (int j = 0; j < ns; j++) {
                // Vbuf bank safety: pointwise of wave w-2 (same parity) must be done
                if (w >= 2 && l < 4) spin_ge(&d_pwdone[4 * j + l], 16 * (w - 1));
                __syncwarp();
                #pragma unroll
                for (int q2 = 0; q2 < 8; q2++)
                    *(float2*)(Vb + j * H_DIM + q2 * 64 + l * 2) =
                        make_float2(v[2 * q2], v[2 * q2 + 1]);
                __threadfence();
                __syncwarp();
                if (l == 0)
                    asm volatile("st.release.gpu.s32 [%0], %1;"
                                 :: "l"(d_vflag + j), "r"(w + 1) : "memory");
                // gates for this step live in mtile 4j
                spin_ge(&d_gemmdone[4 * j], 16 * (w + 1));
                const int r = (t0 + j + 1) % P_INT;
                const __half2* S = Sb2 + (((size_t)(j * B_DIM + r) * NG) >> 1);
                float sf[16], si[16], sg[16];
                load_gate16(S, l, sf);
                load_gate16(S + (H_DIM >> 1), l, si);
                load_gate16(S + ((3 * H_DIM) >> 1), l, sg);
                softmax16(sf);
                softmax16(si);
                #pragma unroll
                for (int q = 0; q < 16; q++)
                    v[q] = tanhf(sf[q] * v[q] + si[q] * tanhf(sg[q]));
            }
        }
        return;
    }

    // ===== worker CTA =====
    const uint32_t sb = smem_u32(smem);
    const int wid = tid >> 5;
    const int l   = tid & 31;
    const int wm = (wid >> 2) * 64;
    const int wn = (wid & 3) * 32;
    const int lrow = l & 15;
    const int lk   = l >> 4;

    uint32_t sA[STG], sBs[STG];
    #pragma unroll
    for (int s = 0; s < STG; s++) {
        sA[s]  = sb + s * (A_SZ + B_SZ);
        sBs[s] = sA[s] + A_SZ;
    }

    for (int w = 0; w < NW; w++) {
        const int t0 = w * P_INT;
        const int ns = (T_LEN - t0 < P_INT) ? (T_LEN - t0) : P_INT;
        const int nmt = ns * 4;
        const int ntile = nmt * 16;
        const int grp = nmt * 4;
        __half* Sb = d_Sbuf + (size_t)(w & 1) * WAVE_S;

        // ---- GEMM tiles (priority: mtile%4==0 group first, feeding the chain) ----
        for (int idx = blockIdx.x; idx < ntile; idx += W) {
            const int mtile = ((idx % grp) >> 4) * 4 + idx / grp;
            const int n0 = (idx & 15) * BN;
            const int m0 = mtile * BM;

            const __half* Xb = d_Xh + ((size_t)t0 * B_DIM + m0) * F_DIM;
            const __half* Hb = d_Hh + (size_t)m0 * H_DIM;
            const __half* Wb = d_Wh + (size_t)n0 * KTOT;

            float acc[4][4][4];
            #pragma unroll
            for (int i = 0; i < 4; i++)
                #pragma unroll
                for (int j = 0; j < 4; j++)
                    #pragma unroll
                    for (int q = 0; q < 4; q++) acc[i][j][q] = 0.0f;

            __syncthreads();   // smem reuse across tiles

            #pragma unroll
            for (int c = 0; c < STG - 1; c++) {       // chunks 0,1: x-only, no spin needed
                load_stage(sA[c], sBs[c], tid, c, Xb, Hb, Wb);
                asm volatile("cp.async.commit_group;" ::: "memory");
            }

            for (int ch = 0; ch < NCH; ch++) {
                asm volatile("cp.async.wait_group 1;" ::: "memory");
                __syncthreads();
                const int cl = ch + STG - 1;
                if (cl == 4)   // first chunk reading d_Hh: wait for pointwise of wave w-1
                    spin_ge(&d_pwdone[mtile], 16 * w);
                if (cl < NCH)
                    load_stage(sA[cl % STG], sBs[cl % STG], tid, cl, Xb, Hb, Wb);
                asm volatile("cp.async.commit_group;" ::: "memory");

                const int s = ch % STG;
                #pragma unroll
                for (int kk = 0; kk < BK / 16; kk++) {
                    uint32_t af[4][4], bfr[2][4];
                    #pragma unroll
                    for (int mi = 0; mi < 4; mi++) {
                        int r = wm + mi * 16 + lrow;
                        int c = kk * 2 + lk;
                        ldm4(af[mi], sA[s] + r * 128 + ((c ^ (r & 7)) * 16));
                    }
                    #pragma unroll
                    for (int bj = 0; bj < 2; bj++) {
                        int r = wn + bj * 16 + lrow;
                        int c = kk * 2 + lk;
                        ldm4(bfr[bj], sBs[s] + r * 128 + ((c ^ (r & 7)) * 16));
                    }
                    #pragma unroll
                    for (int mi = 0; mi < 4; mi++)
                        #pragma unroll
                        for (int nj = 0; nj < 4; nj++)
                            mma16816(acc[mi][nj], af[mi],
                                     bfr[nj >> 1][nj & 1], bfr[nj >> 1][(nj & 1) + 2]);
                }
            }

            // epilogue: bias + fp16 store into this wave's Sbuf bank
            __half2* S2 = (__half2*)Sb;
            #pragma unroll
            for (int mi = 0; mi < 4; mi++) {
                #pragma unroll
                for (int nj = 0; nj < 4; nj++) {
                    int m = m0 + wm + mi * 16 + (l >> 2);
                    int n = n0 + wn + nj * 8 + (l & 3) * 2;
                    float b0 = d_Bcat[n], b1 = d_Bcat[n + 1];
                    S2[((size_t)m * NG + n) >> 1] =
                        __floats2half2_rn(acc[mi][nj][0] + b0, acc[mi][nj][1] + b1);
                    S2[((size_t)(m + 8) * NG + n) >> 1] =
                        __floats2half2_rn(acc[mi][nj][2] + b0, acc[mi][nj][3] + b1);
                }
            }
            __threadfence();
            __syncthreads();
            if (tid == 0) atomicAdd(&d_gemmdone[mtile], 1);
        }

        // ---- pointwise blocks: 8 rows each, warp per row ----
        const int nblk = ns * 64;
        const float* Vb = d_Vbuf + (w & 1) * P_INT * H_DIM;
        const __half2* Sb2 = (const __half2*)Sb;
        for (int b = blockIdx.x; b < nblk; b += W) {
            const int mt = b >> 4;
            const int j  = b >> 6;
            if (tid == 0) spin_ge(&d_gemmdone[mt], 16 * (w + 1));
            __syncthreads();

            const int m = b * 8 + wid;
            const __half2* S = Sb2 + (((size_t)m * NG) >> 1);
            float sf[16], si[16], so[16], sg[16];
            load_gate16(S, l, sf);
            load_gate16(S + (H_DIM >> 1), l, si);
            load_gate16(S + ((2 * H_DIM) >> 1), l, so);
            load_gate16(S + ((3 * H_DIM) >> 1), l, sg);
            softmax16(sf);
            softmax16(si);
            softmax16(so);

            if (tid == 0) spin_ge(&d_vflag[j], w + 1);
            __syncthreads();

            __half2* Hh2 = (__half2*)d_Hh;
            const bool wout = (j == 3);   // ring slot (t0+j)%12 == j; output is slot 3
            #pragma unroll
            for (int q2 = 0; q2 < 8; q2++) {
                float2 vv = *(const float2*)(Vb + j * H_DIM + q2 * 64 + l * 2);
                float c0 = tanhf(sf[2 * q2] * vv.x + si[2 * q2] * tanhf(sg[2 * q2]));
                float c1 = tanhf(sf[2 * q2 + 1] * vv.y + si[2 * q2 + 1] * tanhf(sg[2 * q2 + 1]));
                float h0 = so[2 * q2] * c0;
                float h1 = so[2 * q2 + 1] * c1;
                Hh2[((size_t)m * H_DIM + q2 * 64 + l * 2) >> 1] = __floats2half2_rn(h0, h1);
                if (wout)
                    *(float2*)(out + (size_t)(m & 511) * H_DIM + q2 * 64 + l * 2) =
                        make_float2(h0, h1);
            }
            __threadfence();
            __syncthreads();
            if (tid == 0) atomicAdd(&d_pwdone[mt], 1);
        }
    }
}

// ---------------- launch ----------------
extern "C" void kernel_launch(void* const* d_in, const int* in_sizes, int n_in,
                              void* d_out, int out_size) {
    const float* x  = (const float*)d_in[0];
    const float* Wf = (const float*)d_in[1];
    const float* bf = (const float*)d_in[2];
    const float* Wi = (const float*)d_in[3];
    const float* bi = (const float*)d_in[4];
    const float* Wo = (const float*)d_in[5];
    const float* bo = (const float*)d_in[6];
    const float* Wg = (const float*)d_in[7];
    const float* bg = (const float*)d_in[8];
    float* out = (float*)d_out;

    cudaFuncSetAttribute(persist, cudaFuncAttributeMaxDynamicSharedMemorySize, SMEM_BYTES);

    int sms = 0, occ = 0;
    cudaDeviceGetAttribute(&sms, cudaDevAttrMultiProcessorCount, 0);
    cudaOccupancyMaxActiveBlocksPerMultiprocessor(&occ, persist, 256, SMEM_BYTES);
    if (occ < 1) occ = 1;
    int G = occ * sms;          // guaranteed co-resident (persistent + spin-flags)
    if (G > 297) G = 297;
    if (G < 2) G = 2;

    {
        int n = NG * KTOT;
        pack_kernel<<<(n + 255) / 256, 256>>>(Wf, bf, Wi, bi, Wo, bo, Wg, bg);
    }
    {
        int n = T_LEN * B_DIM * F_DIM;
        convx_kernel<<<n / 256, 256>>>(x);
    }
    {
        int n = P_INT * B_DIM * H_DIM;
        init_kernel<<<(n + 255) / 256, 256>>>();
    }

    persist<<<G, 256, SMEM_BYTES>>>(out);
}

// round 7
// speedup vs baseline: 1.1822x; 1.0240x over previous
#include <cuda_runtime.h>
#include <cuda_fp16.h>
#include <cstdint>
#include <math.h>

#define T_LEN 256
#define B_DIM 512
#define F_DIM 256
#define H_DIM 512
#define P_INT 12
#define KTOT  768
#define NG    2048
#define NW    22            // ceil(256/12)

// ---------------- GEMM tiling (f32-acc mma.sync, at its roofline) ----------------
#define BM 128
#define BN 128
#define BK 64
#define STG 3
#define NCH (KTOT / BK)     // 12

#define A_SZ (BM * BK * 2)  // 16384
#define B_SZ (BN * BK * 2)  // 16384
#define SMEM_BYTES (STG * (A_SZ + B_SZ))  // 96 KB

#define WAVE_ROWS (P_INT * B_DIM)          // 6144
#define WAVE_S ((size_t)WAVE_ROWS * NG)
#define NMT_MAX 48

// task queue: 21 full waves (ns=12 -> 768 gemm + 768 pw = 1536), last wave ns=4 -> 512
#define FULL_TASKS (21 * 1536)
#define TOTAL_TASKS (FULL_TASKS + 512)

// ---------------- static device scratch ----------------
__device__ __half d_Wh[NG * KTOT];
__device__ float  d_Bcat[NG];
__device__ __half d_Xh[T_LEN * B_DIM * F_DIM];
__device__ __half d_Hh[P_INT * B_DIM * H_DIM];
__device__ __half d_Sbuf[2 * WAVE_S];
__device__ float  d_Vbuf[2 * P_INT * H_DIM];
__device__ int    d_gemmdone[NMT_MAX];
__device__ int    d_pwdone[NMT_MAX];
__device__ int    d_vflag[P_INT];
__device__ int    d_qhead;

// ---------------- helpers ----------------
__device__ __forceinline__ uint32_t smem_u32(const void* p) {
    uint32_t a;
    asm("{ .reg .u64 t; cvta.to.shared.u64 t, %1; cvt.u32.u64 %0, t; }" : "=r"(a) : "l"(p));
    return a;
}
__device__ __forceinline__ void cpasync16(uint32_t dst, const void* src) {
    asm volatile("cp.async.cg.shared.global [%0], [%1], 16;"
                 :: "r"(dst), "l"(__cvta_generic_to_global(src)) : "memory");
}
__device__ __forceinline__ void ldm4(uint32_t* r, uint32_t addr) {
    asm volatile("ldmatrix.sync.aligned.m8n8.x4.shared.b16 {%0,%1,%2,%3}, [%4];"
                 : "=r"(r[0]), "=r"(r[1]), "=r"(r[2]), "=r"(r[3]) : "r"(addr));
}
__device__ __forceinline__ void mma16816(float* d, const uint32_t* a, uint32_t b0, uint32_t b1) {
    asm volatile(
        "mma.sync.aligned.m16n8k16.row.col.f32.f16.f16.f32 "
        "{%0,%1,%2,%3}, {%4,%5,%6,%7}, {%8,%9}, {%0,%1,%2,%3};"
        : "+f"(d[0]), "+f"(d[1]), "+f"(d[2]), "+f"(d[3])
        : "r"(a[0]), "r"(a[1]), "r"(a[2]), "r"(a[3]), "r"(b0), "r"(b1));
}
__device__ __forceinline__ int ld_acq(const int* p) {
    int v;
    asm volatile("ld.acquire.gpu.s32 %0, [%1];" : "=r"(v) : "l"(p) : "memory");
    return v;
}
__device__ __forceinline__ void spin_ge(const int* p, int tgt) {
    if (ld_acq(p) >= tgt) return;
    while (ld_acq(p) < tgt) __nanosleep(128);
}

// ---------------- pack / convert / init ----------------
__global__ void pack_kernel(const float* __restrict__ Wf, const float* __restrict__ bf,
                            const float* __restrict__ Wi, const float* __restrict__ bi,
                            const float* __restrict__ Wo, const float* __restrict__ bo,
                            const float* __restrict__ Wg, const float* __restrict__ bg) {
    int idx = blockIdx.x * blockDim.x + threadIdx.x;
    if (idx < NG * KTOT) {
        int n = idx / KTOT;
        int k = idx % KTOT;
        int g = n >> 9, h = n & 511;
        const float* W = (g == 0) ? Wf : (g == 1) ? Wi : (g == 2) ? Wo : Wg;
        d_Wh[idx] = __float2half(W[k * H_DIM + h]);
    }
    if (idx < NG) {
        int g = idx / H_DIM, h = idx % H_DIM;
        const float* bb = (g == 0) ? bf : (g == 1) ? bi : (g == 2) ? bo : bg;
        d_Bcat[idx] = bb[h];
    }
}

__global__ void convx_kernel(const float* __restrict__ x) {
    int i = blockIdx.x * blockDim.x + threadIdx.x;
    d_Xh[i] = __float2half(x[i]);
}

__global__ void init_kernel() {
    int i = blockIdx.x * blockDim.x + threadIdx.x;
    if (i < P_INT * B_DIM * H_DIM) d_Hh[i] = __float2half(0.0f);
    if (i < NMT_MAX) { d_gemmdone[i] = 0; d_pwdone[i] = 0; }
    if (i < P_INT) d_vflag[i] = 0;
    if (i == 0) d_qhead = 0;
}

// ---------------- stage loader ----------------
__device__ __forceinline__ void load_stage(uint32_t sa, uint32_t sbB, int tid, int ch,
                                           const __half* Xb, const __half* Hb, const __half* Wb) {
    const int k0 = ch * BK;
    const __half* asrc;
    int astride;
    if (k0 < F_DIM) { asrc = Xb + k0;           astride = F_DIM; }
    else            { asrc = Hb + (k0 - F_DIM); astride = H_DIM; }
    #pragma unroll
    for (int i = 0; i < 4; i++) {
        int cell = tid + i * 256;
        int r = cell >> 3, c = cell & 7;
        cpasync16(sa + r * 128 + ((c ^ (r & 7)) * 16),
                  asrc + (size_t)r * astride + c * 8);
    }
    #pragma unroll
    for (int i = 0; i < 4; i++) {
        int cell = tid + i * 256;
        int r = cell >> 3, c = cell & 7;
        cpasync16(sbB + r * 128 + ((c ^ (r & 7)) * 16),
                  Wb + (size_t)r * KTOT + k0 + c * 8);
    }
}

// ---------------- warp softmax over 512 values (16 per lane) ----------------
__device__ __forceinline__ void softmax16(float* s) {
    float mx = -1e30f;
    #pragma unroll
    for (int q = 0; q < 16; q++) mx = fmaxf(mx, s[q]);
    #pragma unroll
    for (int o = 16; o > 0; o >>= 1) mx = fmaxf(mx, __shfl_xor_sync(0xffffffffu, mx, o));
    float sum = 0.0f;
    #pragma unroll
    for (int q = 0; q < 16; q++) { s[q] = __expf(s[q] - mx); sum += s[q]; }
    #pragma unroll
    for (int o = 16; o > 0; o >>= 1) sum += __shfl_xor_sync(0xffffffffu, sum, o);
    const float inv = 1.0f / sum;
    #pragma unroll
    for (int q = 0; q < 16; q++) s[q] *= inv;
}
// element q of lane l <-> column (q>>1)*64 + l*2 + (q&1)
__device__ __forceinline__ void load_gate16(const __half2* base, int l, float* s) {
    #pragma unroll
    for (int q2 = 0; q2 < 8; q2++) {
        float2 v = __half22float2(base[q2 * 32 + l]);
        s[2 * q2] = v.x;
        s[2 * q2 + 1] = v.y;
    }
}

// ---------------- persistent fused kernel (global task queue) ----------------
__global__ void __launch_bounds__(256, 2) persist(float* __restrict__ out) {
    extern __shared__ char smem[];
    const int G = gridDim.x;
    const int tid = threadIdx.x;

    if ((int)blockIdx.x == G - 1) {
        // ===== chain CTA: one warp, register-resident v across ALL waves =====
        if (tid >= 32) return;
        const int l = tid;
        float v[16];
        #pragma unroll
        for (int q = 0; q < 16; q++) v[q] = 0.0f;

        for (int w = 0; w < NW; w++) {
            const int t0 = w * P_INT;
            const int ns = (T_LEN - t0 < P_INT) ? (T_LEN - t0) : P_INT;
            const __half2* Sb2 = (const __half2*)(d_Sbuf + (size_t)(w & 1) * WAVE_S);
            float* Vb = d_Vbuf + (w & 1) * P_INT * H_DIM;
            for (int j = 0; j < ns; j++) {
                if (w >= 2 && l < 4) spin_ge(&d_pwdone[4 * j + l], 16 * (w - 1));
                __syncwarp();
                #pragma unroll
                for (int q2 = 0; q2 < 8; q2++)
                    *(float2*)(Vb + j * H_DIM + q2 * 64 + l * 2) =
                        make_float2(v[2 * q2], v[2 * q2 + 1]);
                __threadfence();
                __syncwarp();
                if (l == 0)
                    asm volatile("st.release.gpu.s32 [%0], %1;"
                                 :: "l"(d_vflag + j), "r"(w + 1) : "memory");
                spin_ge(&d_gemmdone[4 * j], 16 * (w + 1));
                const int r = (t0 + j + 1) % P_INT;
                const __half2* S = Sb2 + (((size_t)(j * B_DIM + r) * NG) >> 1);
                float sf[16], si[16], sg[16];
                load_gate16(S, l, sf);
                load_gate16(S + (H_DIM >> 1), l, si);
                load_gate16(S + ((3 * H_DIM) >> 1), l, sg);
                softmax16(sf);
                softmax16(si);
                #pragma unroll
                for (int q = 0; q < 16; q++)
                    v[q] = tanhf(sf[q] * v[q] + si[q] * tanhf(sg[q]));
            }
        }
        return;
    }

    // ===== worker CTA: pull tasks from the global queue =====
    __shared__ int s_task;
    const uint32_t sb = smem_u32(smem);
    const int wid = tid >> 5;
    const int l   = tid & 31;
    const int wm = (wid >> 2) * 64;
    const int wn = (wid & 3) * 32;
    const int lrow = l & 15;
    const int lk   = l >> 4;

    uint32_t sA[STG], sBs[STG];
    #pragma unroll
    for (int s = 0; s < STG; s++) {
        sA[s]  = sb + s * (A_SZ + B_SZ);
        sBs[s] = sA[s] + A_SZ;
    }

    while (true) {
        __syncthreads();
        if (tid == 0) s_task = atomicAdd(&d_qhead, 1);
        __syncthreads();
        const int task = s_task;
        if (task >= TOTAL_TASKS) break;

        int w, r, ns;
        if (task < FULL_TASKS) { w = task / 1536; r = task % 1536; ns = 12; }
        else                   { w = 21; r = task - FULL_TASKS; ns = 4; }
        const int t0 = w * P_INT;
        const int ntile = ns * 64;     // gemm tasks this wave (= ns*4 mtiles * 16)
        __half* Sb = d_Sbuf + (size_t)(w & 1) * WAVE_S;

        if (r < ntile) {
            // ---- GEMM tile (chain-feeding mtiles first within the wave) ----
            const int grp = ns * 16;
            const int mtile = ((r % grp) >> 4) * 4 + r / grp;
            const int n0 = (r & 15) * BN;
            const int m0 = mtile * BM;

            const __half* Xb = d_Xh + ((size_t)t0 * B_DIM + m0) * F_DIM;
            const __half* Hb = d_Hh + (size_t)m0 * H_DIM;
            const __half* Wb = d_Wh + (size_t)n0 * KTOT;

            float acc[4][4][4];
            #pragma unroll
            for (int i = 0; i < 4; i++)
                #pragma unroll
                for (int j = 0; j < 4; j++)
                    #pragma unroll
                    for (int q = 0; q < 4; q++) acc[i][j][q] = 0.0f;

            #pragma unroll
            for (int c = 0; c < STG - 1; c++) {     // chunks 0,1 read x only
                load_stage(sA[c], sBs[c], tid, c, Xb, Hb, Wb);
                asm volatile("cp.async.commit_group;" ::: "memory");
            }

            for (int ch = 0; ch < NCH; ch++) {
                asm volatile("cp.async.wait_group 1;" ::: "memory");
                __syncthreads();
                const int cl = ch + STG - 1;
                if (cl == 4)   // first chunk reading d_Hh: need pointwise of wave w-1
                    spin_ge(&d_pwdone[mtile], 16 * w);
                if (cl < NCH)
                    load_stage(sA[cl % STG], sBs[cl % STG], tid, cl, Xb, Hb, Wb);
                asm volatile("cp.async.commit_group;" ::: "memory");

                const int s = ch % STG;
                #pragma unroll
                for (int kk = 0; kk < BK / 16; kk++) {
                    uint32_t af[4][4], bfr[2][4];
                    #pragma unroll
                    for (int mi = 0; mi < 4; mi++) {
                        int rr = wm + mi * 16 + lrow;
                        int cc = kk * 2 + lk;
                        ldm4(af[mi], sA[s] + rr * 128 + ((cc ^ (rr & 7)) * 16));
                    }
                    #pragma unroll
                    for (int bj = 0; bj < 2; bj++) {
                        int rr = wn + bj * 16 + lrow;
                        int cc = kk * 2 + lk;
                        ldm4(bfr[bj], sBs[s] + rr * 128 + ((cc ^ (rr & 7)) * 16));
                    }
                    #pragma unroll
                    for (int mi = 0; mi < 4; mi++)
                        #pragma unroll
                        for (int nj = 0; nj < 4; nj++)
                            mma16816(acc[mi][nj], af[mi],
                                     bfr[nj >> 1][nj & 1], bfr[nj >> 1][(nj & 1) + 2]);
                }
            }

            __half2* S2 = (__half2*)Sb;
            #pragma unroll
            for (int mi = 0; mi < 4; mi++) {
                #pragma unroll
                for (int nj = 0; nj < 4; nj++) {
                    int m = m0 + wm + mi * 16 + (l >> 2);
                    int n = n0 + wn + nj * 8 + (l & 3) * 2;
                    float b0 = d_Bcat[n], b1 = d_Bcat[n + 1];
                    S2[((size_t)m * NG + n) >> 1] =
                        __floats2half2_rn(acc[mi][nj][0] + b0, acc[mi][nj][1] + b1);
                    S2[((size_t)(m + 8) * NG + n) >> 1] =
                        __floats2half2_rn(acc[mi][nj][2] + b0, acc[mi][nj][3] + b1);
                }
            }
            __threadfence();
            __syncthreads();
            if (tid == 0) atomicAdd(&d_gemmdone[mtile], 1);
        } else {
            // ---- pointwise block: 8 rows, warp per row ----
            const int b = r - ntile;
            const int mt = b >> 4;
            const int j  = b >> 6;
            if (tid == 0) spin_ge(&d_gemmdone[mt], 16 * (w + 1));
            __syncthreads();

            const int m = b * 8 + wid;
            const float* Vb = d_Vbuf + (w & 1) * P_INT * H_DIM;
            const __half2* S = (const __half2*)Sb + (((size_t)m * NG) >> 1);
            float sf[16], si[16], so[16], sg[16];
            load_gate16(S, l, sf);
            load_gate16(S + (H_DIM >> 1), l, si);
            load_gate16(S + ((2 * H_DIM) >> 1), l, so);
            load_gate16(S + ((3 * H_DIM) >> 1), l, sg);
            softmax16(sf);
            softmax16(si);
            softmax16(so);

            if (tid == 0) spin_ge(&d_vflag[j], w + 1);
            __syncthreads();

            __half2* Hh2 = (__half2*)d_Hh;
            const bool wout = (j == 3);   // ring slot 3 feeds the output
            #pragma unroll
            for (int q2 = 0; q2 < 8; q2++) {
                float2 vv = *(const float2*)(Vb + j * H_DIM + q2 * 64 + l * 2);
                float c0 = tanhf(sf[2 * q2] * vv.x + si[2 * q2] * tanhf(sg[2 * q2]));
                float c1 = tanhf(sf[2 * q2 + 1] * vv.y + si[2 * q2 + 1] * tanhf(sg[2 * q2 + 1]));
                float h0 = so[2 * q2] * c0;
                float h1 = so[2 * q2 + 1] * c1;
                Hh2[((size_t)m * H_DIM + q2 * 64 + l * 2) >> 1] = __floats2half2_rn(h0, h1);
                if (wout)
                    *(float2*)(out + (size_t)(m & 511) * H_DIM + q2 * 64 + l * 2) =
                        make_float2(h0, h1);
            }
            __threadfence();
            __syncthreads();
            if (tid == 0) atomicAdd(&d_pwdone[mt], 1);
        }
    }
}

// ---------------- launch ----------------
extern "C" void kernel_launch(void* const* d_in, const int* in_sizes, int n_in,
                              void* d_out, int out_size) {
    const float* x  = (const float*)d_in[0];
    const float* Wf = (const float*)d_in[1];
    const float* bf = (const float*)d_in[2];
    const float* Wi = (const float*)d_in[3];
    const float* bi = (const float*)d_in[4];
    const float* Wo = (const float*)d_in[5];
    const float* bo = (const float*)d_in[6];
    const float* Wg = (const float*)d_in[7];
    const float* bg = (const float*)d_in[8];
    float* out = (float*)d_out;

    cudaFuncSetAttribute(persist, cudaFuncAttributeMaxDynamicSharedMemorySize, SMEM_BYTES);

    int sms = 0, occ = 0;
    cudaDeviceGetAttribute(&sms, cudaDevAttrMultiProcessorCount, 0);
    cudaOccupancyMaxActiveBlocksPerMultiprocessor(&occ, persist, 256, SMEM_BYTES);
    if (occ < 1) occ = 1;
    int G = occ * sms;
    if (G > 297) G = 297;
    if (G < 2) G = 2;

    {
        int n = NG * KTOT;
        pack_kernel<<<(n + 255) / 256, 256>>>(Wf, bf, Wi, bi, Wo, bo, Wg, bg);
    }
    {
        int n = T_LEN * B_DIM * F_DIM;
        convx_kernel<<<n / 256, 256>>>(x);
    }
    {
        int n = P_INT * B_DIM * H_DIM;
        init_kernel<<<(n + 255) / 256, 256>>>();
    }

    persist<<<G, 256, SMEM_BYTES>>>(out);
}

// round 8
// speedup vs baseline: 1.2151x; 1.0278x over previous
#include <cuda_runtime.h>
#include <cuda_fp16.h>
#include <cstdint>
#include <math.h>

#define T_LEN 256
#define B_DIM 512
#define F_DIM 256
#define H_DIM 512
#define P_INT 12
#define KTOT  768
#define NG    2048
#define NW    22

// ---------------- GEMM tiling ----------------
#define BM 128
#define BN 128
#define BK 64
#define STG 3
#define NCH (KTOT / BK)

#define A_SZ (BM * BK * 2)
#define B_SZ (BN * BK * 2)
#define SMEM_BYTES (STG * (A_SZ + B_SZ))  // 96 KB

#define WAVE_ROWS (P_INT * B_DIM)
#define WAVE_S ((size_t)WAVE_ROWS * NG)
#define NMT_MAX 48

// tasks: 21 full waves (768 gemm + 768 pw = 1536); pruned last wave: 112 gemm + 64 pw
#define FULL_TASKS (21 * 1536)
#define LAST_GEMM 112
#define LAST_TASKS (LAST_GEMM + 64)
#define TOTAL_TASKS (FULL_TASKS + LAST_TASKS)

__device__ __constant__ int c_lastmt[7] = {0, 4, 8, 12, 13, 14, 15};

// ---------------- static device scratch ----------------
__device__ __half d_Wh[NG * KTOT];
__device__ float  d_Bcat[NG];
__device__ __half d_Xh[T_LEN * B_DIM * F_DIM];
__device__ __half d_Hh[P_INT * B_DIM * H_DIM];
__device__ __half d_Sbuf[2 * WAVE_S];
__device__ float  d_Vbuf[2 * P_INT * H_DIM];
__device__ int    d_gemmdone[NMT_MAX];
__device__ int    d_pwdone[NMT_MAX];
__device__ int    d_vflag[P_INT];
__device__ int    d_qhead;

// ---------------- helpers ----------------
__device__ __forceinline__ uint32_t smem_u32(const void* p) {
    uint32_t a;
    asm("{ .reg .u64 t; cvta.to.shared.u64 t, %1; cvt.u32.u64 %0, t; }" : "=r"(a) : "l"(p));
    return a;
}
__device__ __forceinline__ void cpasync16(uint32_t dst, const void* src) {
    asm volatile("cp.async.cg.shared.global [%0], [%1], 16;"
                 :: "r"(dst), "l"(__cvta_generic_to_global(src)) : "memory");
}
__device__ __forceinline__ void ldm4(uint32_t* r, uint32_t addr) {
    asm volatile("ldmatrix.sync.aligned.m8n8.x4.shared.b16 {%0,%1,%2,%3}, [%4];"
                 : "=r"(r[0]), "=r"(r[1]), "=r"(r[2]), "=r"(r[3]) : "r"(addr));
}
__device__ __forceinline__ void mma16816(float* d, const uint32_t* a, uint32_t b0, uint32_t b1) {
    asm volatile(
        "mma.sync.aligned.m16n8k16.row.col.f32.f16.f16.f32 "
        "{%0,%1,%2,%3}, {%4,%5,%6,%7}, {%8,%9}, {%0,%1,%2,%3};"
        : "+f"(d[0]), "+f"(d[1]), "+f"(d[2]), "+f"(d[3])
        : "r"(a[0]), "r"(a[1]), "r"(a[2]), "r"(a[3]), "r"(b0), "r"(b1));
}
__device__ __forceinline__ int ld_acq(const int* p) {
    int v;
    asm volatile("ld.acquire.gpu.s32 %0, [%1];" : "=r"(v) : "l"(p) : "memory");
    return v;
}
__device__ __forceinline__ void spin_hot(const int* p, int tgt) {
    while (ld_acq(p) < tgt) { }
}
__device__ __forceinline__ void spin_bk(const int* p, int tgt) {
    if (ld_acq(p) >= tgt) return;
    while (ld_acq(p) < tgt) __nanosleep(64);
}
__device__ __forceinline__ void done_release(int* p) {
    asm volatile("red.release.gpu.global.add.s32 [%0], %1;"
                 :: "l"(__cvta_generic_to_global(p)), "r"(1) : "memory");
}
__device__ __forceinline__ float tanh_fast(float x) {
    float y;
    asm("tanh.approx.f32 %0, %1;" : "=f"(y) : "f"(x));
    return y;
}

// ---------------- pack / convert / init ----------------
__global__ void pack_kernel(const float* __restrict__ Wf, const float* __restrict__ bf,
                            const float* __restrict__ Wi, const float* __restrict__ bi,
                            const float* __restrict__ Wo, const float* __restrict__ bo,
                            const float* __restrict__ Wg, const float* __restrict__ bg) {
    int idx = blockIdx.x * blockDim.x + threadIdx.x;
    if (idx < NG * KTOT) {
        int n = idx / KTOT;
        int k = idx % KTOT;
        int g = n >> 9, h = n & 511;
        const float* W = (g == 0) ? Wf : (g == 1) ? Wi : (g == 2) ? Wo : Wg;
        d_Wh[idx] = __float2half(W[k * H_DIM + h]);
    }
    if (idx < NG) {
        int g = idx / H_DIM, h = idx % H_DIM;
        const float* bb = (g == 0) ? bf : (g == 1) ? bi : (g == 2) ? bo : bg;
        d_Bcat[idx] = bb[h];
    }
}

__global__ void convx_kernel(const float* __restrict__ x) {
    int i = blockIdx.x * blockDim.x + threadIdx.x;
    d_Xh[i] = __float2half(x[i]);
}

__global__ void init_kernel() {
    int i = blockIdx.x * blockDim.x + threadIdx.x;
    if (i < P_INT * B_DIM * H_DIM) d_Hh[i] = __float2half(0.0f);
    if (i < NMT_MAX) { d_gemmdone[i] = 0; d_pwdone[i] = 0; }
    if (i < P_INT) d_vflag[i] = 0;
    if (i == 0) d_qhead = 0;
}

// ---------------- stage loader ----------------
__device__ __forceinline__ void load_stage(uint32_t sa, uint32_t sbB, int tid, int ch,
                                           const __half* Xb, const __half* Hb, const __half* Wb) {
    const int k0 = ch * BK;
    const __half* asrc;
    int astride;
    if (k0 < F_DIM) { asrc = Xb + k0;           astride = F_DIM; }
    else            { asrc = Hb + (k0 - F_DIM); astride = H_DIM; }
    #pragma unroll
    for (int i = 0; i < 4; i++) {
        int cell = tid + i * 256;
        int r = cell >> 3, c = cell & 7;
        cpasync16(sa + r * 128 + ((c ^ (r & 7)) * 16),
                  asrc + (size_t)r * astride + c * 8);
    }
    #pragma unroll
    for (int i = 0; i < 4; i++) {
        int cell = tid + i * 256;
        int r = cell >> 3, c = cell & 7;
        cpasync16(sbB + r * 128 + ((c ^ (r & 7)) * 16),
                  Wb + (size_t)r * KTOT + k0 + c * 8);
    }
}

// ---------------- warp softmax over 512 values (16 per lane) ----------------
__device__ __forceinline__ void softmax16(float* s) {
    float mx = -1e30f;
    #pragma unroll
    for (int q = 0; q < 16; q++) mx = fmaxf(mx, s[q]);
    #pragma unroll
    for (int o = 16; o > 0; o >>= 1) mx = fmaxf(mx, __shfl_xor_sync(0xffffffffu, mx, o));
    float sum = 0.0f;
    #pragma unroll
    for (int q = 0; q < 16; q++) { s[q] = __expf(s[q] - mx); sum += s[q]; }
    #pragma unroll
    for (int o = 16; o > 0; o >>= 1) sum += __shfl_xor_sync(0xffffffffu, sum, o);
    const float inv = 1.0f / sum;
    #pragma unroll
    for (int q = 0; q < 16; q++) s[q] *= inv;
}
// element q of lane l <-> column (q>>1)*64 + l*2 + (q&1)
__device__ __forceinline__ void load_gate16(const __half2* base, int l, float* s) {
    #pragma unroll
    for (int q2 = 0; q2 < 8; q2++) {
        float2 v = __half22float2(base[q2 * 32 + l]);
        s[2 * q2] = v.x;
        s[2 * q2 + 1] = v.y;
    }
}

// ---------------- persistent fused kernel ----------------
__global__ void __launch_bounds__(256, 2) persist(float* __restrict__ out) {
    extern __shared__ char smem[];
    const int G = gridDim.x;
    const int tid = threadIdx.x;

    if ((int)blockIdx.x == G - 1) {
        // ===== chain CTA: one warp, register-resident v across ALL waves =====
        if (tid >= 32) return;
        const int l = tid;
        float v[16];
        #pragma unroll
        for (int q = 0; q < 16; q++) v[q] = 0.0f;

        for (int w = 0; w < NW; w++) {
            const int t0 = w * P_INT;
            const int ns = (T_LEN - t0 < P_INT) ? (T_LEN - t0) : P_INT;
            const __half2* Sb2 = (const __half2*)(d_Sbuf + (size_t)(w & 1) * WAVE_S);
            float* Vb = d_Vbuf + (w & 1) * P_INT * H_DIM;
            for (int j = 0; j < ns; j++) {
                if (w >= 2 && l < 4) spin_hot(&d_pwdone[4 * j + l], 16 * (w - 1));
                __syncwarp();
                #pragma unroll
                for (int q2 = 0; q2 < 8; q2++)
                    *(float2*)(Vb + j * H_DIM + q2 * 64 + l * 2) =
                        make_float2(v[2 * q2], v[2 * q2 + 1]);
                __threadfence();
                __syncwarp();
                if (l == 0)
                    asm volatile("st.release.gpu.s32 [%0], %1;"
                                 :: "l"(d_vflag + j), "r"(w + 1) : "memory");
                spin_hot(&d_gemmdone[4 * j], 16 * (w + 1));
                const int r = (t0 + j + 1) % P_INT;
                const __half2* S = Sb2 + (((size_t)(j * B_DIM + r) * NG) >> 1);
                float sf[16], si[16], sg[16];
                load_gate16(S, l, sf);
                load_gate16(S + (H_DIM >> 1), l, si);
                load_gate16(S + ((3 * H_DIM) >> 1), l, sg);
                softmax16(sf);
                softmax16(si);
                #pragma unroll
                for (int q = 0; q < 16; q++)
                    v[q] = tanh_fast(sf[q] * v[q] + si[q] * tanh_fast(sg[q]));
            }
        }
        return;
    }

    // ===== worker CTA: global task queue =====
    __shared__ int s_task;
    const uint32_t sb = smem_u32(smem);
    const int wid = tid >> 5;
    const int l   = tid & 31;
    const int wm = (wid >> 2) * 64;
    const int wn = (wid & 3) * 32;
    const int lrow = l & 15;
    const int lk   = l >> 4;

    uint32_t sA[STG], sBs[STG];
    #pragma unroll
    for (int s = 0; s < STG; s++) {
        sA[s]  = sb + s * (A_SZ + B_SZ);
        sBs[s] = sA[s] + A_SZ;
    }

    while (true) {
        __syncthreads();
        if (tid == 0) s_task = atomicAdd(&d_qhead, 1);
        __syncthreads();
        const int task = s_task;
        if (task >= TOTAL_TASKS) break;

        int w, r, ns, ntile;
        bool is_gemm;
        int mtile = 0, n0 = 0, pwb = 0;
        if (task < FULL_TASKS) {
            w = task / 1536; r = task % 1536; ns = 12; ntile = 768;
            if (r < ntile) {
                is_gemm = true;
                const int grp = ns * 16;
                mtile = ((r % grp) >> 4) * 4 + r / grp;
                n0 = (r & 15) * BN;
            } else {
                is_gemm = false;
                pwb = r - ntile;
            }
        } else {
            w = 21; r = task - FULL_TASKS; ns = 4;
            if (r < LAST_GEMM) {
                is_gemm = true;
                mtile = c_lastmt[r >> 4];
                n0 = (r & 15) * BN;
            } else {
                is_gemm = false;
                pwb = 192 + (r - LAST_GEMM);   // only j==3 blocks
            }
        }
        const int t0 = w * P_INT;
        __half* Sb = d_Sbuf + (size_t)(w & 1) * WAVE_S;

        if (is_gemm) {
            const int m0 = mtile * BM;
            const __half* Xb = d_Xh + ((size_t)t0 * B_DIM + m0) * F_DIM;
            const __half* Hb = d_Hh + (size_t)m0 * H_DIM;
            const __half* Wb = d_Wh + (size_t)n0 * KTOT;

            float acc[4][4][4];
            #pragma unroll
            for (int i = 0; i < 4; i++)
                #pragma unroll
                for (int j = 0; j < 4; j++)
                    #pragma unroll
                    for (int q = 0; q < 4; q++) acc[i][j][q] = 0.0f;

            #pragma unroll
            for (int c = 0; c < STG - 1; c++) {
                load_stage(sA[c], sBs[c], tid, c, Xb, Hb, Wb);
                asm volatile("cp.async.commit_group;" ::: "memory");
            }

            for (int ch = 0; ch < NCH; ch++) {
                asm volatile("cp.async.wait_group 1;" ::: "memory");
                __syncthreads();
                const int cl = ch + STG - 1;
                if (cl == 4)
                    spin_bk(&d_pwdone[mtile], 16 * w);
                if (cl < NCH)
                    load_stage(sA[cl % STG], sBs[cl % STG], tid, cl, Xb, Hb, Wb);
                asm volatile("cp.async.commit_group;" ::: "memory");

                const int s = ch % STG;
                #pragma unroll
                for (int kk = 0; kk < BK / 16; kk++) {
                    uint32_t af[4][4], bfr[2][4];
                    #pragma unroll
                    for (int mi = 0; mi < 4; mi++) {
                        int rr = wm + mi * 16 + lrow;
                        int cc = kk * 2 + lk;
                        ldm4(af[mi], sA[s] + rr * 128 + ((cc ^ (rr & 7)) * 16));
                    }
                    #pragma unroll
                    for (int bj = 0; bj < 2; bj++) {
                        int rr = wn + bj * 16 + lrow;
                        int cc = kk * 2 + lk;
                        ldm4(bfr[bj], sBs[s] + rr * 128 + ((cc ^ (rr & 7)) * 16));
                    }
                    #pragma unroll
                    for (int mi = 0; mi < 4; mi++)
                        #pragma unroll
                        for (int nj = 0; nj < 4; nj++)
                            mma16816(acc[mi][nj], af[mi],
                                     bfr[nj >> 1][nj & 1], bfr[nj >> 1][(nj & 1) + 2]);
                }
            }

            __half2* S2 = (__half2*)Sb;
            #pragma unroll
            for (int mi = 0; mi < 4; mi++) {
                #pragma unroll
                for (int nj = 0; nj < 4; nj++) {
                    int m = m0 + wm + mi * 16 + (l >> 2);
                    int n = n0 + wn + nj * 8 + (l & 3) * 2;
                    float b0 = d_Bcat[n], b1 = d_Bcat[n + 1];
                    S2[((size_t)m * NG + n) >> 1] =
                        __floats2half2_rn(acc[mi][nj][0] + b0, acc[mi][nj][1] + b1);
                    S2[((size_t)(m + 8) * NG + n) >> 1] =
                        __floats2half2_rn(acc[mi][nj][2] + b0, acc[mi][nj][3] + b1);
                }
            }
            __syncthreads();
            if (tid == 0) done_release(&d_gemmdone[mtile]);
        } else {
            // ---- pointwise block: 8 rows, warp per row ----
            const int b = pwb;
            const int mt = b >> 4;
            const int j  = b >> 6;
            if (tid == 0) spin_bk(&d_gemmdone[mt], 16 * (w + 1));
            __syncthreads();

            const int m = b * 8 + wid;
            const float* Vb = d_Vbuf + (w & 1) * P_INT * H_DIM;
            const __half2* S = (const __half2*)Sb + (((size_t)m * NG) >> 1);
            float sf[16], si[16], so[16], sg[16];
            load_gate16(S, l, sf);
            load_gate16(S + (H_DIM >> 1), l, si);
            load_gate16(S + ((2 * H_DIM) >> 1), l, so);
            load_gate16(S + ((3 * H_DIM) >> 1), l, sg);
            softmax16(sf);
            softmax16(si);
            softmax16(so);

            if (tid == 0) spin_bk(&d_vflag[j], w + 1);
            __syncthreads();

            __half2* Hh2 = (__half2*)d_Hh;
            const bool wout = (j == 3);
            #pragma unroll
            for (int q2 = 0; q2 < 8; q2++) {
                float2 vv = *(const float2*)(Vb + j * H_DIM + q2 * 64 + l * 2);
                float c0 = tanh_fast(sf[2 * q2] * vv.x + si[2 * q2] * tanh_fast(sg[2 * q2]));
                float c1 = tanh_fast(sf[2 * q2 + 1] * vv.y + si[2 * q2 + 1] * tanh_fast(sg[2 * q2 + 1]));
                float h0 = so[2 * q2] * c0;
                float h1 = so[2 * q2 + 1] * c1;
                Hh2[((size_t)m * H_DIM + q2 * 64 + l * 2) >> 1] = __floats2half2_rn(h0, h1);
                if (wout)
                    *(float2*)(out + (size_t)(m & 511) * H_DIM + q2 * 64 + l * 2) =
                        make_float2(h0, h1);
            }
            __syncthreads();
            if (tid == 0) done_release(&d_pwdone[mt]);
        }
    }
}

// ---------------- launch ----------------
extern "C" void kernel_launch(void* const* d_in, const int* in_sizes, int n_in,
                              void* d_out, int out_size) {
    const float* x  = (const float*)d_in[0];
    const float* Wf = (const float*)d_in[1];
    const float* bf = (const float*)d_in[2];
    const float* Wi = (const float*)d_in[3];
    const float* bi = (const float*)d_in[4];
    const float* Wo = (const float*)d_in[5];
    const float* bo = (const float*)d_in[6];
    const float* Wg = (const float*)d_in[7];
    const float* bg = (const float*)d_in[8];
    float* out = (float*)d_out;

    cudaFuncSetAttribute(persist, cudaFuncAttributeMaxDynamicSharedMemorySize, SMEM_BYTES);

    int sms = 0, occ = 0;
    cudaDeviceGetAttribute(&sms, cudaDevAttrMultiProcessorCount, 0);
    cudaOccupancyMaxActiveBlocksPerMultiprocessor(&occ, persist, 256, SMEM_BYTES);
    if (occ < 1) occ = 1;
    int G = occ * sms;
    if (G > 297) G = 297;
    if (G < 2) G = 2;

    {
        int n = NG * KTOT;
        pack_kernel<<<(n + 255) / 256, 256>>>(Wf, bf, Wi, bi, Wo, bo, Wg, bg);
    }
    {
        int n = T_LEN * B_DIM * F_DIM;
        convx_kernel<<<n / 256, 256>>>(x);
    }
    {
        int n = P_INT * B_DIM * H_DIM;
        init_kernel<<<(n + 255) / 256, 256>>>();
    }

    persist<<<G, 256, SMEM_BYTES>>>(out);
}